// round 10
// baseline (speedup 1.0000x reference)
#include <cuda_runtime.h>
#include <cuda_bf16.h>
#include <math.h>
#include <stdint.h>

#define FULL 0xFFFFFFFFu

constexpr int Hh = 16, Ee = 64;
constexpr int QT      = 128;   // queries per block (filter)
constexpr int KTile   = 128;   // keys per tile
constexpr int T1      = 512;   // threads filter
constexpr int ASTR    = 400;   // bytes per smem A/B row (384 data + 16 pad)
constexpr int CAP     = 256;   // candidate cap per query
constexpr int NROWS   = 2048 * 16;           // rows per tensor (T*H / S*H max)
constexpr int NQ      = NROWS;

// smem layout (filter)
constexpr int A_OFF  = 0;                    // 128 x 400
constexpr int B0_OFF = QT * ASTR;            // 51200
constexpr int B1_OFF = B0_OFF + KTile * ASTR;
constexpr int SMEM1  = B1_OFF + KTile * ASTR + 16;

// global scratch
__device__ uint4              g_Qs[(size_t)NROWS * 24];   // [h][t] rows of 384B: [hiQ|hiQ|loQ]
__device__ uint4              g_Ks[(size_t)NROWS * 24];   // [h][s] rows of 384B: [hiK|loK|hiK]
__device__ float              g_thr[NROWS];               // per (h*T+t) threshold
__device__ unsigned long long g_cand[(size_t)NQ * CAP];   // packed (fmap<<11 | inv_idx)
__device__ int                g_cnt[NQ];

__device__ __forceinline__ unsigned fmap(float f) {
    unsigned u = __float_as_uint(f);
    return (u & 0x80000000u) ? ~u : (u | 0x80000000u);
}
__device__ __forceinline__ float funmap(unsigned u) {
    return (u & 0x80000000u) ? __uint_as_float(u ^ 0x80000000u) : __uint_as_float(~u);
}
__device__ __forceinline__ void ldsm4(uint32_t& r0, uint32_t& r1, uint32_t& r2, uint32_t& r3,
                                      uint32_t a) {
    asm volatile("ldmatrix.sync.aligned.m8n8.x4.shared.b16 {%0,%1,%2,%3}, [%4];"
                 : "=r"(r0), "=r"(r1), "=r"(r2), "=r"(r3) : "r"(a));
}
__device__ __forceinline__ void hmma(float* c, uint32_t a0, uint32_t a1, uint32_t a2, uint32_t a3,
                                     uint32_t b0, uint32_t b1) {
    asm volatile(
        "mma.sync.aligned.m16n8k16.row.col.f32.bf16.bf16.f32 "
        "{%0,%1,%2,%3}, {%4,%5,%6,%7}, {%8,%9}, {%0,%1,%2,%3};"
        : "+f"(c[0]), "+f"(c[1]), "+f"(c[2]), "+f"(c[3])
        : "r"(a0), "r"(a1), "r"(a2), "r"(a3), "r"(b0), "r"(b1));
}
__device__ __forceinline__ void cpasync16(uint32_t sdst, const void* gsrc) {
    asm volatile("cp.async.cg.shared.global [%0], [%1], 16;" :: "r"(sdst), "l"(gsrc));
}

// ================= prep: split fp32 -> (hi,lo) bf16 rows + thresholds =================
// ONE ROW PER WARP: launch with (nrows + 7) / 8 blocks of 256 threads.
__global__ void __launch_bounds__(256, 8)
prep_kernel(const float* __restrict__ Q, const float* __restrict__ K, int T, int S)
{
    const int row  = blockIdx.x * 8 + (threadIdx.x >> 5);
    const int lane = threadIdx.x & 31;
    const int qrows = T * Hh;

    if (row < qrows) {                       // Q row: t = row/Hh, h = row%Hh
        const int t = row / Hh, h = row % Hh;
        float2 f = *reinterpret_cast<const float2*>(Q + (size_t)row * Ee + lane * 2);
        f.x *= 0.125f; f.y *= 0.125f;
        float ssq = f.x * f.x + f.y * f.y;
        #pragma unroll
        for (int o = 16; o; o >>= 1) ssq += __shfl_xor_sync(FULL, ssq, o);
        __nv_bfloat162 hi = __floats2bfloat162_rn(f.x, f.y);
        float2 hf = __bfloat1622float2(hi);
        __nv_bfloat162 lo = __floats2bfloat162_rn(f.x - hf.x, f.y - hf.y);
        uint32_t* drow = reinterpret_cast<uint32_t*>(&g_Qs[(size_t)(h * T + t) * 24]);
        drow[lane]      = *reinterpret_cast<uint32_t*>(&hi);
        drow[lane + 32] = *reinterpret_cast<uint32_t*>(&hi);
        drow[lane + 64] = *reinterpret_cast<uint32_t*>(&lo);
        if (lane == 0) g_thr[h * T + t] = 1.6f * sqrtf(ssq);
    } else {                                 // K row
        const int r2 = row - qrows;
        if (r2 >= S * Hh) return;
        const int s = r2 / Hh, h = r2 % Hh;
        float2 f = *reinterpret_cast<const float2*>(K + (size_t)r2 * Ee + lane * 2);
        __nv_bfloat162 hi = __floats2bfloat162_rn(f.x, f.y);
        float2 hf = __bfloat1622float2(hi);
        __nv_bfloat162 lo = __floats2bfloat162_rn(f.x - hf.x, f.y - hf.y);
        uint32_t* drow = reinterpret_cast<uint32_t*>(&g_Ks[(size_t)(h * S + s) * 24]);
        drow[lane]      = *reinterpret_cast<uint32_t*>(&hi);
        drow[lane + 32] = *reinterpret_cast<uint32_t*>(&lo);
        drow[lane + 64] = *reinterpret_cast<uint32_t*>(&hi);
    }
}

// ================= filter: MMA scores + threshold collect =================
__global__ void __launch_bounds__(T1, 1)
filter_kernel(int T, int S)
{
    extern __shared__ char smc[];
    const uint32_t smem = (uint32_t)__cvta_generic_to_shared(smc);

    const int h = blockIdx.y, tid = threadIdx.x;
    const int warp = tid >> 5, lane = tid & 31;
    const int tbase = blockIdx.x * QT;
    const int ntiles = S / KTile;

    // prologue: A tile (128 rows) + B tile 0, one cp.async group
    {
        const char* asrc = reinterpret_cast<const char*>(&g_Qs[(size_t)(h * T + tbase) * 24]);
        #pragma unroll
        for (int i = 0; i < (QT * 24) / T1; i++) {       // 6 chunks
            int idx = i * T1 + tid;
            int row = idx / 24, c = idx % 24;
            cpasync16(smem + A_OFF + row * ASTR + c * 16, asrc + (size_t)row * 384 + c * 16);
        }
        const char* bsrc = reinterpret_cast<const char*>(&g_Ks[(size_t)(h * S) * 24]);
        #pragma unroll
        for (int i = 0; i < (KTile * 24) / T1; i++) {
            int idx = i * T1 + tid;
            int row = idx / 24, c = idx % 24;
            cpasync16(smem + B0_OFF + row * ASTR + c * 16, bsrc + (size_t)row * 384 + c * 16);
        }
        asm volatile("cp.async.commit_group;");
    }

    // warp quadrant: 16 queries x 64 keys
    const int qs = (warp >> 1) * 16;
    const int kb = (warp & 1) * 64;
    const uint32_t aBase = smem + A_OFF + (uint32_t)(qs + (lane & 15)) * ASTR
                         + (uint32_t)(lane >> 4) * 16u;
    const uint32_t bOff  = (uint32_t)(kb + (lane & 7) + ((lane >> 4) << 3)) * ASTR
                         + (uint32_t)((lane >> 3) & 1) * 16u;

    const int r = lane >> 2, cc = (lane & 3) * 2;
    const float thr0 = g_thr[h * T + tbase + qs + r];
    const float thr1 = g_thr[h * T + tbase + qs + 8 + r];
    const int qg0 = (tbase + qs + r) * Hh + h;
    const int qg1 = qg0 + 8 * Hh;

    #pragma unroll 1
    for (int kt = 0; kt < ntiles; kt++) {
        // issue next B tile (buffer swap); previous-iteration trailing sync guarantees
        // the target buffer is no longer being read
        if (kt + 1 < ntiles) {
            const char* bsrc = reinterpret_cast<const char*>(
                &g_Ks[(size_t)(h * S + (kt + 1) * KTile) * 24]);
            uint32_t bdst = smem + (((kt + 1) & 1) ? B1_OFF : B0_OFF);
            #pragma unroll
            for (int i = 0; i < (KTile * 24) / T1; i++) {
                int idx = i * T1 + tid;
                int row = idx / 24, c = idx % 24;
                cpasync16(bdst + row * ASTR + c * 16, bsrc + (size_t)row * 384 + c * 16);
            }
            asm volatile("cp.async.commit_group;");
            asm volatile("cp.async.wait_group 1;");
        } else {
            asm volatile("cp.async.wait_group 0;");
        }
        __syncthreads();   // tile kt visible to all warps

        const uint32_t bBase = smem + ((kt & 1) ? B1_OFF : B0_OFF) + bOff;

        float c4[8][4];
        #pragma unroll
        for (int nt = 0; nt < 8; nt++)
            { c4[nt][0] = 0.f; c4[nt][1] = 0.f; c4[nt][2] = 0.f; c4[nt][3] = 0.f; }
        #pragma unroll
        for (int ks = 0; ks < 12; ks++) {
            uint32_t a0, a1, a2, a3;
            ldsm4(a0, a1, a2, a3, aBase + ks * 32);
            #pragma unroll
            for (int jp = 0; jp < 4; jp++) {
                uint32_t b0, b1, b2, b3;
                ldsm4(b0, b1, b2, b3, bBase + ks * 32 + jp * 16 * ASTR);
                hmma(c4[2 * jp],     a0, a1, a2, a3, b0, b1);
                hmma(c4[2 * jp + 1], a0, a1, a2, a3, b2, b3);
            }
        }

        // collect candidates straight from fragments
        #pragma unroll
        for (int nt = 0; nt < 8; nt++) {
            int k0 = kt * KTile + kb + nt * 8 + cc;
            #pragma unroll
            for (int half = 0; half < 2; half++) {
                float s0 = c4[nt][2 * half], s1 = c4[nt][2 * half + 1];
                float th = half ? thr1 : thr0;
                int   qg = half ? qg1 : qg0;
                if (s0 > th) {
                    int slot = atomicAdd(&g_cnt[qg], 1);
                    if (slot < CAP)
                        g_cand[(size_t)qg * CAP + slot] =
                            ((unsigned long long)fmap(s0) << 11) | (unsigned)(S - 1 - k0);
                }
                if (s1 > th) {
                    int slot = atomicAdd(&g_cnt[qg], 1);
                    if (slot < CAP)
                        g_cand[(size_t)qg * CAP + slot] =
                            ((unsigned long long)fmap(s1) << 11) | (unsigned)(S - 2 - k0);
                }
            }
        }
        __syncthreads();   // all reads of buf[kt&1] done before it is re-targeted
    }
}

// ================= select: exact top-32 + softmax + V gather =================
__global__ void __launch_bounds__(256, 4)
select_kernel(const float* __restrict__ Q, const float* __restrict__ K,
              const float* __restrict__ V, float* __restrict__ O, int S)
{
    const int warp = threadIdx.x >> 5, lane = threadIdx.x & 31;
    const int qg = blockIdx.x * 8 + warp;
    const int t = qg / Hh, h = qg % Hh;

    const int c = min(g_cnt[qg], CAP);
    unsigned long long key[8];
    #pragma unroll
    for (int j = 0; j < 8; j++) {
        int s = j * 32 + lane;
        key[j] = (s < c) ? g_cand[(size_t)qg * CAP + s] : 0ull;
    }

    constexpr unsigned long long KMASK = 0x7FFFFFFFFFFull;   // 43-bit key space

    auto radix = [&]() -> unsigned long long {
        // warp-wide common prefix of valid keys
        unsigned long long av = KMASK, ov = 0ull;
        #pragma unroll
        for (int j = 0; j < 8; j++) {
            if (key[j]) { av &= key[j]; ov |= key[j]; }
        }
        #pragma unroll
        for (int o = 16; o; o >>= 1) {
            av &= __shfl_xor_sync(FULL, av, o);
            ov |= __shfl_xor_sync(FULL, ov, o);
        }
        unsigned long long diff = (av ^ ov) | 1ull;
        int hb = 63 - __clzll(diff);
        if (hb > 42) hb = 42;
        unsigned long long res = av & ~((2ull << hb) - 1ull);
        for (int b = hb; b >= 0; b--) {
            unsigned long long tt = res | (1ull << b);
            int cq = 0;
            #pragma unroll
            for (int j = 0; j < 8; j++)
                cq += __popc(__ballot_sync(FULL, key[j] >= tt));
            if (cq >= 32) res = tt;
            if (cq == 32) break;
        }
        return res;
    };
    unsigned long long res = radix();

    // exact rescore of boundary band (4096 fmap-ulps)
    {
        bool any = false;
        long long rf = (long long)(res >> 11);
        #pragma unroll
        for (int j = 0; j < 8; j++) {
            if (key[j]) {
                long long d = (long long)(key[j] >> 11) - rf;
                if (d <= 4096 && d >= -4096) any = true;
            }
        }
        if (__ballot_sync(FULL, any)) {
            const float4* qr = reinterpret_cast<const float4*>(Q + ((size_t)t * Hh + h) * Ee);
            #pragma unroll 1
            for (int j = 0; j < 8; j++) {
                if (!key[j]) continue;
                long long d = (long long)(key[j] >> 11) - rf;
                if (d > 4096 || d < -4096) continue;
                int idx = S - 1 - (int)(key[j] & 0x7FFull);
                const float4* kr = reinterpret_cast<const float4*>(K + ((size_t)idx * Hh + h) * Ee);
                float acc = 0.f;
                #pragma unroll
                for (int e = 0; e < 16; e++) {
                    float4 qv = qr[e], kv = __ldg(kr + e);
                    acc += qv.x * kv.x + qv.y * kv.y + qv.z * kv.z + qv.w * kv.w;
                }
                acc *= 0.125f;
                key[j] = ((unsigned long long)fmap(acc) << 11) | (key[j] & 0x7FFull);
            }
            res = radix();
        }
    }

    // softmax over kept
    bool keep[8]; float sc[8];
    float mx = -INFINITY;
    #pragma unroll
    for (int j = 0; j < 8; j++) {
        keep[j] = key[j] && key[j] >= res;
        sc[j] = keep[j] ? funmap((unsigned)(key[j] >> 11)) : -INFINITY;
        mx = fmaxf(mx, sc[j]);
    }
    #pragma unroll
    for (int o = 16; o; o >>= 1) mx = fmaxf(mx, __shfl_xor_sync(FULL, mx, o));
    float w[8]; float Z = 0.f;
    #pragma unroll
    for (int j = 0; j < 8; j++) {
        w[j] = keep[j] ? __expf(sc[j] - mx) : 0.f;
        Z += w[j];
    }
    #pragma unroll
    for (int o = 16; o; o >>= 1) Z += __shfl_xor_sync(FULL, Z, o);
    const float rz = 1.f / fmaxf(Z, 1e-30f);

    const float2* V2 = reinterpret_cast<const float2*>(V);
    float2 acc = make_float2(0.f, 0.f);
    #pragma unroll 1
    for (int j = 0; j < 8; j++) {
        unsigned msk = __ballot_sync(FULL, keep[j]);
        while (msk) {
            int src = __ffs(msk) - 1; msk &= msk - 1;
            float wv = __shfl_sync(FULL, w[j], src) * rz;
            unsigned kk = (unsigned)__shfl_sync(FULL, (int)(key[j] & 0x7FFull), src);
            int ij = S - 1 - (int)kk;
            float2 vv = V2[((size_t)ij * Hh + h) * 32 + lane];
            acc.x += wv * vv.x; acc.y += wv * vv.y;
        }
    }
    reinterpret_cast<float2*>(O + ((size_t)t * Hh + h) * Ee)[lane] = acc;
}

extern "C" void kernel_launch(void* const* d_in, const int* in_sizes, int n_in,
                              void* d_out, int out_size)
{
    const float* Q = (const float*)d_in[0];
    const float* K = (const float*)d_in[1];
    const float* V = (const float*)d_in[2];
    float*       O = (float*)d_out;

    const int T = in_sizes[0] / (Hh * Ee);
    const int S = in_sizes[1] / (Hh * Ee);

    void* cntPtr = nullptr;
    cudaGetSymbolAddress(&cntPtr, g_cnt);
    cudaMemsetAsync(cntPtr, 0, sizeof(int) * NQ);

    const int nrows = (T + S) * Hh;
    prep_kernel<<<(nrows + 7) / 8, 256>>>(Q, K, T, S);   // 8 rows per block (1/warp)

    cudaFuncSetAttribute(filter_kernel,
                         cudaFuncAttributeMaxDynamicSharedMemorySize, SMEM1);
    dim3 grid1(T / QT, Hh);
    filter_kernel<<<grid1, T1, SMEM1>>>(T, S);

    select_kernel<<<(T * Hh) / 8, 256>>>(Q, K, V, O, S);
}

// round 11
// speedup vs baseline: 1.5194x; 1.5194x over previous
#include <cuda_runtime.h>
#include <cuda_bf16.h>
#include <math.h>
#include <stdint.h>

#define FULL 0xFFFFFFFFu

constexpr int Hh = 16, Ee = 64;
constexpr int QT      = 128;   // queries per block (filter)
constexpr int KTile   = 128;   // keys per tile
constexpr int T1      = 512;   // threads filter
constexpr int RB      = 272;   // bytes per smem A/B row (256 data + 16 pad)
constexpr int CAP     = 256;   // candidate cap per query
constexpr int NROWS   = 2048 * 16;
constexpr int NQ      = NROWS;

// smem layout (filter)
constexpr int A_OFF  = 0;                      // 128 x 272 = 34816
constexpr int B0_OFF = QT * RB;                // 34816
constexpr int B1_OFF = B0_OFF + KTile * RB;    // 69632
constexpr int SMEM1  = B1_OFF + KTile * RB + 16;   // 104464

// global scratch: rows of 256B = [hi(128B) | lo(128B)]
__device__ uint4              g_Qs[(size_t)NROWS * 16];
__device__ uint4              g_Ks[(size_t)NROWS * 16];
__device__ float              g_thr[NROWS];
__device__ unsigned long long g_cand[(size_t)NQ * CAP];
__device__ int                g_cnt[NQ];

__device__ __forceinline__ unsigned fmap(float f) {
    unsigned u = __float_as_uint(f);
    return (u & 0x80000000u) ? ~u : (u | 0x80000000u);
}
__device__ __forceinline__ float funmap(unsigned u) {
    return (u & 0x80000000u) ? __uint_as_float(u ^ 0x80000000u) : __uint_as_float(~u);
}
__device__ __forceinline__ void ldsm4(uint32_t& r0, uint32_t& r1, uint32_t& r2, uint32_t& r3,
                                      uint32_t a) {
    asm volatile("ldmatrix.sync.aligned.m8n8.x4.shared.b16 {%0,%1,%2,%3}, [%4];"
                 : "=r"(r0), "=r"(r1), "=r"(r2), "=r"(r3) : "r"(a));
}
__device__ __forceinline__ void hmma(float* c, uint32_t a0, uint32_t a1, uint32_t a2, uint32_t a3,
                                     uint32_t b0, uint32_t b1) {
    asm volatile(
        "mma.sync.aligned.m16n8k16.row.col.f32.bf16.bf16.f32 "
        "{%0,%1,%2,%3}, {%4,%5,%6,%7}, {%8,%9}, {%0,%1,%2,%3};"
        : "+f"(c[0]), "+f"(c[1]), "+f"(c[2]), "+f"(c[3])
        : "r"(a0), "r"(a1), "r"(a2), "r"(a3), "r"(b0), "r"(b1));
}
__device__ __forceinline__ void cpasync16(uint32_t sdst, const void* gsrc) {
    asm volatile("cp.async.cg.shared.global [%0], [%1], 16;" :: "r"(sdst), "l"(gsrc));
}

// ================= prep: split fp32 -> [hi|lo] bf16 rows + thresholds =================
// ONE ROW PER WARP: launch with (nrows + 7) / 8 blocks of 256 threads.
__global__ void __launch_bounds__(256, 8)
prep_kernel(const float* __restrict__ Q, const float* __restrict__ K, int T, int S)
{
    const int row  = blockIdx.x * 8 + (threadIdx.x >> 5);
    const int lane = threadIdx.x & 31;
    const int qrows = T * Hh;

    if (row < qrows) {                       // Q row
        const int t = row / Hh, h = row % Hh;
        float2 f = *reinterpret_cast<const float2*>(Q + (size_t)row * Ee + lane * 2);
        f.x *= 0.125f; f.y *= 0.125f;
        float ssq = f.x * f.x + f.y * f.y;
        #pragma unroll
        for (int o = 16; o; o >>= 1) ssq += __shfl_xor_sync(FULL, ssq, o);
        __nv_bfloat162 hi = __floats2bfloat162_rn(f.x, f.y);
        float2 hf = __bfloat1622float2(hi);
        __nv_bfloat162 lo = __floats2bfloat162_rn(f.x - hf.x, f.y - hf.y);
        uint32_t* drow = reinterpret_cast<uint32_t*>(&g_Qs[(size_t)(h * T + t) * 16]);
        drow[lane]      = *reinterpret_cast<uint32_t*>(&hi);
        drow[lane + 32] = *reinterpret_cast<uint32_t*>(&lo);
        if (lane == 0) g_thr[h * T + t] = 1.6f * sqrtf(ssq);
    } else {                                 // K row
        const int r2 = row - qrows;
        if (r2 >= S * Hh) return;
        const int s = r2 / Hh, h = r2 % Hh;
        float2 f = *reinterpret_cast<const float2*>(K + (size_t)r2 * Ee + lane * 2);
        __nv_bfloat162 hi = __floats2bfloat162_rn(f.x, f.y);
        float2 hf = __bfloat1622float2(hi);
        __nv_bfloat162 lo = __floats2bfloat162_rn(f.x - hf.x, f.y - hf.y);
        uint32_t* drow = reinterpret_cast<uint32_t*>(&g_Ks[(size_t)(h * S + s) * 16]);
        drow[lane]      = *reinterpret_cast<uint32_t*>(&hi);
        drow[lane + 32] = *reinterpret_cast<uint32_t*>(&lo);
    }
}

// ================= filter: MMA scores + threshold collect =================
__global__ void __launch_bounds__(T1, 2)
filter_kernel(int T, int S)
{
    extern __shared__ char smc[];
    const uint32_t smem = (uint32_t)__cvta_generic_to_shared(smc);

    const int h = blockIdx.y, tid = threadIdx.x;
    const int warp = tid >> 5, lane = tid & 31;
    const int tbase = blockIdx.x * QT;
    const int ntiles = S / KTile;

    // prologue: A tile + B tile 0 (rows of 256B = 16 chunks)
    {
        const char* asrc = reinterpret_cast<const char*>(&g_Qs[(size_t)(h * T + tbase) * 16]);
        #pragma unroll
        for (int i = 0; i < (QT * 16) / T1; i++) {
            int idx = i * T1 + tid;
            int row = idx >> 4, c = idx & 15;
            cpasync16(smem + A_OFF + row * RB + c * 16, asrc + (size_t)row * 256 + c * 16);
        }
        const char* bsrc = reinterpret_cast<const char*>(&g_Ks[(size_t)(h * S) * 16]);
        #pragma unroll
        for (int i = 0; i < (KTile * 16) / T1; i++) {
            int idx = i * T1 + tid;
            int row = idx >> 4, c = idx & 15;
            cpasync16(smem + B0_OFF + row * RB + c * 16, bsrc + (size_t)row * 256 + c * 16);
        }
        asm volatile("cp.async.commit_group;");
    }

    // warp tile: 16 queries x 64 keys, processed as two 32-key halves
    const int qs = (warp >> 1) * 16;
    const int kwarp = (warp & 1) * 64;
    const uint32_t aBase = smem + A_OFF + (uint32_t)(qs + (lane & 15)) * RB
                         + (uint32_t)(lane >> 4) * 16u;
    const uint32_t bRowSel = (uint32_t)((lane & 7) + ((lane >> 4) << 3)) * RB
                           + (uint32_t)((lane >> 3) & 1) * 16u;

    const int r = lane >> 2, cc = (lane & 3) * 2;
    const float thr0 = g_thr[h * T + tbase + qs + r];
    const float thr1 = g_thr[h * T + tbase + qs + 8 + r];
    const int qg0 = (tbase + qs + r) * Hh + h;
    const int qg1 = qg0 + 8 * Hh;

    // K=192 as 12 ks-steps: group g = ks>>2 uses A-block [hi,hi,lo], B-block [hi,lo,hi]
    #pragma unroll 1
    for (int kt = 0; kt < ntiles; kt++) {
        if (kt + 1 < ntiles) {
            const char* bsrc = reinterpret_cast<const char*>(
                &g_Ks[(size_t)(h * S + (kt + 1) * KTile) * 16]);
            uint32_t bdst = smem + (((kt + 1) & 1) ? B1_OFF : B0_OFF);
            #pragma unroll
            for (int i = 0; i < (KTile * 16) / T1; i++) {
                int idx = i * T1 + tid;
                int row = idx >> 4, c = idx & 15;
                cpasync16(bdst + row * RB + c * 16, bsrc + (size_t)row * 256 + c * 16);
            }
            asm volatile("cp.async.commit_group;");
            asm volatile("cp.async.wait_group 1;");
        } else {
            asm volatile("cp.async.wait_group 0;");
        }
        __syncthreads();

        const uint32_t bufBase = smem + ((kt & 1) ? B1_OFF : B0_OFF);

        #pragma unroll
        for (int half = 0; half < 2; half++) {
            const int kb = kwarp + half * 32;
            const uint32_t bBase = bufBase + (uint32_t)kb * RB + bRowSel;

            float c4[4][4];
            #pragma unroll
            for (int nt = 0; nt < 4; nt++)
                { c4[nt][0] = 0.f; c4[nt][1] = 0.f; c4[nt][2] = 0.f; c4[nt][3] = 0.f; }

            #pragma unroll
            for (int ks = 0; ks < 12; ks++) {
                const int g = ks >> 2, sub = ks & 3;
                const uint32_t aOff = (g == 2 ? 128u : 0u) + sub * 32u;
                const uint32_t bOff = (g == 1 ? 128u : 0u) + sub * 32u;
                uint32_t a0, a1, a2, a3;
                ldsm4(a0, a1, a2, a3, aBase + aOff);
                #pragma unroll
                for (int jp = 0; jp < 2; jp++) {
                    uint32_t b0, b1, b2, b3;
                    ldsm4(b0, b1, b2, b3, bBase + bOff + jp * 16 * RB);
                    hmma(c4[2 * jp],     a0, a1, a2, a3, b0, b1);
                    hmma(c4[2 * jp + 1], a0, a1, a2, a3, b2, b3);
                }
            }

            // collect candidates straight from fragments
            #pragma unroll
            for (int nt = 0; nt < 4; nt++) {
                int k0 = kt * KTile + kb + nt * 8 + cc;
                #pragma unroll
                for (int hv = 0; hv < 2; hv++) {
                    float s0 = c4[nt][2 * hv], s1 = c4[nt][2 * hv + 1];
                    float th = hv ? thr1 : thr0;
                    int   qg = hv ? qg1 : qg0;
                    if (s0 > th) {
                        int slot = atomicAdd(&g_cnt[qg], 1);
                        if (slot < CAP)
                            g_cand[(size_t)qg * CAP + slot] =
                                ((unsigned long long)fmap(s0) << 11) | (unsigned)(S - 1 - k0);
                    }
                    if (s1 > th) {
                        int slot = atomicAdd(&g_cnt[qg], 1);
                        if (slot < CAP)
                            g_cand[(size_t)qg * CAP + slot] =
                                ((unsigned long long)fmap(s1) << 11) | (unsigned)(S - 2 - k0);
                    }
                }
            }
        }
        __syncthreads();
    }
}

// ================= select: exact top-32 + softmax + V gather =================
__global__ void __launch_bounds__(256, 4)
select_kernel(const float* __restrict__ Q, const float* __restrict__ K,
              const float* __restrict__ V, float* __restrict__ O, int S)
{
    const int warp = threadIdx.x >> 5, lane = threadIdx.x & 31;
    const int qg = blockIdx.x * 8 + warp;
    const int t = qg / Hh, h = qg % Hh;

    const int c = min(g_cnt[qg], CAP);
    unsigned long long key[8];
    #pragma unroll
    for (int j = 0; j < 8; j++) {
        int s = j * 32 + lane;
        key[j] = (s < c) ? g_cand[(size_t)qg * CAP + s] : 0ull;
    }

    constexpr unsigned long long KMASK = 0x7FFFFFFFFFFull;

    auto radix = [&]() -> unsigned long long {
        unsigned long long av = KMASK, ov = 0ull;
        #pragma unroll
        for (int j = 0; j < 8; j++) {
            if (key[j]) { av &= key[j]; ov |= key[j]; }
        }
        #pragma unroll
        for (int o = 16; o; o >>= 1) {
            av &= __shfl_xor_sync(FULL, av, o);
            ov |= __shfl_xor_sync(FULL, ov, o);
        }
        unsigned long long diff = (av ^ ov) | 1ull;
        int hb = 63 - __clzll(diff);
        if (hb > 42) hb = 42;
        unsigned long long res = av & ~((2ull << hb) - 1ull);
        for (int b = hb; b >= 0; b--) {
            unsigned long long tt = res | (1ull << b);
            int cq = 0;
            #pragma unroll
            for (int j = 0; j < 8; j++)
                cq += __popc(__ballot_sync(FULL, key[j] >= tt));
            if (cq >= 32) res = tt;
            if (cq == 32) break;
        }
        return res;
    };
    unsigned long long res = radix();

    // exact rescore of boundary band (4096 fmap-ulps)
    {
        bool any = false;
        long long rf = (long long)(res >> 11);
        #pragma unroll
        for (int j = 0; j < 8; j++) {
            if (key[j]) {
                long long d = (long long)(key[j] >> 11) - rf;
                if (d <= 4096 && d >= -4096) any = true;
            }
        }
        if (__ballot_sync(FULL, any)) {
            const float4* qr = reinterpret_cast<const float4*>(Q + ((size_t)t * Hh + h) * Ee);
            #pragma unroll 1
            for (int j = 0; j < 8; j++) {
                if (!key[j]) continue;
                long long d = (long long)(key[j] >> 11) - rf;
                if (d > 4096 || d < -4096) continue;
                int idx = S - 1 - (int)(key[j] & 0x7FFull);
                const float4* kr = reinterpret_cast<const float4*>(K + ((size_t)idx * Hh + h) * Ee);
                float acc = 0.f;
                #pragma unroll
                for (int e = 0; e < 16; e++) {
                    float4 qv = qr[e], kv = __ldg(kr + e);
                    acc += qv.x * kv.x + qv.y * kv.y + qv.z * kv.z + qv.w * kv.w;
                }
                acc *= 0.125f;
                key[j] = ((unsigned long long)fmap(acc) << 11) | (key[j] & 0x7FFull);
            }
            res = radix();
        }
    }

    // softmax over kept
    bool keep[8]; float sc[8];
    float mx = -INFINITY;
    #pragma unroll
    for (int j = 0; j < 8; j++) {
        keep[j] = key[j] && key[j] >= res;
        sc[j] = keep[j] ? funmap((unsigned)(key[j] >> 11)) : -INFINITY;
        mx = fmaxf(mx, sc[j]);
    }
    #pragma unroll
    for (int o = 16; o; o >>= 1) mx = fmaxf(mx, __shfl_xor_sync(FULL, mx, o));
    float w[8]; float Z = 0.f;
    #pragma unroll
    for (int j = 0; j < 8; j++) {
        w[j] = keep[j] ? __expf(sc[j] - mx) : 0.f;
        Z += w[j];
    }
    #pragma unroll
    for (int o = 16; o; o >>= 1) Z += __shfl_xor_sync(FULL, Z, o);
    const float rz = 1.f / fmaxf(Z, 1e-30f);

    const float2* V2 = reinterpret_cast<const float2*>(V);
    float2 acc = make_float2(0.f, 0.f);
    #pragma unroll 1
    for (int j = 0; j < 8; j++) {
        unsigned msk = __ballot_sync(FULL, keep[j]);
        while (msk) {
            int src = __ffs(msk) - 1; msk &= msk - 1;
            float wv = __shfl_sync(FULL, w[j], src) * rz;
            unsigned kk = (unsigned)__shfl_sync(FULL, (int)(key[j] & 0x7FFull), src);
            int ij = S - 1 - (int)kk;
            float2 vv = V2[((size_t)ij * Hh + h) * 32 + lane];
            acc.x += wv * vv.x; acc.y += wv * vv.y;
        }
    }
    reinterpret_cast<float2*>(O + ((size_t)t * Hh + h) * Ee)[lane] = acc;
}

extern "C" void kernel_launch(void* const* d_in, const int* in_sizes, int n_in,
                              void* d_out, int out_size)
{
    const float* Q = (const float*)d_in[0];
    const float* K = (const float*)d_in[1];
    const float* V = (const float*)d_in[2];
    float*       O = (float*)d_out;

    const int T = in_sizes[0] / (Hh * Ee);
    const int S = in_sizes[1] / (Hh * Ee);

    const int nrows = (T + S) * Hh;
    prep_kernel<<<(nrows + 7) / 8, 256>>>(Q, K, T, S);

    cudaFuncSetAttribute(filter_kernel,
                         cudaFuncAttributeMaxDynamicSharedMemorySize, SMEM1);
    dim3 grid1(T / QT, Hh);
    filter_kernel<<<grid1, T1, SMEM1>>>(T, S);

    select_kernel<<<(T * Hh) / 8, 256>>>(Q, K, V, O, S);

    // zero counters for the NEXT call (g_cnt is statically zero on first use;
    // keeping the memset last makes launch #6 in the stream the filter kernel
    // so ncu's -s 5 -c 1 captures it)
    void* cntPtr = nullptr;
    cudaGetSymbolAddress(&cntPtr, g_cnt);
    cudaMemsetAsync(cntPtr, 0, sizeof(int) * NQ);
}